// round 2
// baseline (speedup 1.0000x reference)
#include <cuda_runtime.h>
#include <math.h>

#define NN 50000
#define EE 800000
#define F 128
#define OUTC 10
#define GG 64

// ---------------- scratch (device globals; no allocation allowed) ----------
__device__ __align__(16) float g_deg[NN];
__device__ __align__(16) float g_dinv[NN];
__device__ __align__(16) float g_nself[NN];
__device__ __align__(16) int   g_cnt[NN];
__device__ __align__(16) int   g_fill[NN];
__device__ __align__(16) int   g_rowptr[NN + 1];
__device__ __align__(16) int   g_csrc[EE];
__device__ __align__(16) float g_cval[EE];
__device__ __align__(16) float g_h1[NN * F];
__device__ __align__(16) float g_h2[NN * F];
__device__ __align__(16) float g_h3[NN * OUTC];
__device__ __align__(16) float g_pool[GG * OUTC];
__device__ __align__(16) float g_pcnt[GG];
__device__ __align__(16) int   g_bsum[256];

// ---------------- f32x2 packed-FMA helpers ----------------------------------
__device__ __forceinline__ unsigned long long pack2(float x) {
    unsigned long long r;
    asm("mov.b64 %0, {%1, %1};" : "=l"(r) : "f"(x));
    return r;
}
__device__ __forceinline__ void ffma2(unsigned long long& acc,
                                      unsigned long long a,
                                      unsigned long long b) {
    asm("fma.rn.f32x2 %0, %1, %2, %0;" : "+l"(acc) : "l"(a), "l"(b));
}
__device__ __forceinline__ float lo32(unsigned long long a) {
    return __uint_as_float((unsigned)(a & 0xffffffffull));
}
__device__ __forceinline__ float hi32(unsigned long long a) {
    return __uint_as_float((unsigned)(a >> 32));
}

// ---------------- init ------------------------------------------------------
__global__ void k_zero() {
    int i = blockIdx.x * blockDim.x + threadIdx.x;
    if (i < NN) { g_deg[i] = 0.f; g_cnt[i] = 0; g_fill[i] = 0; }
    if (i < GG * OUTC) g_pool[i] = 0.f;
    if (i < GG) g_pcnt[i] = 0.f;
}

// degree (weighted, by dst) + in-degree histogram
__global__ void k_deg(const int* __restrict__ ei, const float* __restrict__ ew) {
    int e = blockIdx.x * blockDim.x + threadIdx.x;
    if (e >= EE) return;
    int d = ei[EE + e];
    atomicAdd(&g_deg[d], ew[e]);
    atomicAdd(&g_cnt[d], 1);
}

// fused: dinv + per-block exclusive scan of cnt
__global__ void k_scan1() {
    __shared__ int s[256];
    int tid = threadIdx.x;
    int i = blockIdx.x * 256 + tid;
    if (i < NN) {
        float di = rsqrtf(g_deg[i] + 1.0f);
        g_dinv[i] = di;
        g_nself[i] = di * di;
    }
    int v = (i < NN) ? g_cnt[i] : 0;
    s[tid] = v; __syncthreads();
#pragma unroll
    for (int off = 1; off < 256; off <<= 1) {
        int t = (tid >= off) ? s[tid - off] : 0;
        __syncthreads();
        s[tid] += t;
        __syncthreads();
    }
    if (i < NN) g_rowptr[i] = s[tid] - v;
    if (tid == 255) g_bsum[blockIdx.x] = s[255];
}

__global__ void k_scan2(int nblk) {
    __shared__ int s[256];
    int tid = threadIdx.x;
    int v = (tid < nblk) ? g_bsum[tid] : 0;
    s[tid] = v; __syncthreads();
#pragma unroll
    for (int off = 1; off < 256; off <<= 1) {
        int t = (tid >= off) ? s[tid - off] : 0;
        __syncthreads();
        s[tid] += t;
        __syncthreads();
    }
    if (tid < nblk) g_bsum[tid] = s[tid] - v;
}

__global__ void k_scan3() {
    int i = blockIdx.x * blockDim.x + threadIdx.x;
    if (i < NN) g_rowptr[i] += g_bsum[i >> 8];
    if (i == 0) g_rowptr[NN] = EE;
}

// scatter edges into per-dst buckets, storing src + norm value
__global__ void k_fill(const int* __restrict__ ei, const float* __restrict__ ew) {
    int e = blockIdx.x * blockDim.x + threadIdx.x;
    if (e >= EE) return;
    int s = ei[e];
    int d = ei[EE + e];
    float nv = g_dinv[s] * ew[e] * g_dinv[d];
    int p = g_rowptr[d] + atomicAdd(&g_fill[d], 1);
    g_csrc[p] = s;
    g_cval[p] = nv;
}

// ---------------- dense GEMM (f32x2): Y[nr,128] = X[nr,128] @ W[128,128] ----
// 256 thr, tile 64x128, thread = 4 rows x 8 cols (4 f32x2 col-pairs/row)
__global__ void __launch_bounds__(256) k_gemm128(
    const float* __restrict__ X, const float* __restrict__ W,
    float* __restrict__ Y, int nrows)
{
    extern __shared__ float smem[];
    float* Ws = smem;              // 128*128
    float* Xs = smem + F * F;      // 64*128
    int tid = threadIdx.x;
    for (int i = tid * 4; i < F * F; i += 1024)
        *(float4*)&Ws[i] = *(const float4*)&W[i];
    int row0 = blockIdx.x * 64;
    for (int i = tid * 4; i < 64 * F; i += 1024) {
        int r = row0 + (i >> 7);
        float4 v = make_float4(0.f, 0.f, 0.f, 0.f);
        if (r < nrows) v = *(const float4*)&X[r * F + (i & 127)];
        *(float4*)&Xs[i] = v;
    }
    __syncthreads();

    int tx = tid & 15;   // col group: 8 cols at tx*8
    int ty = tid >> 4;   // row group: 4 rows at ty*4

    unsigned long long acc[4][4];
#pragma unroll
    for (int r = 0; r < 4; r++)
#pragma unroll
        for (int p = 0; p < 4; p++) acc[r][p] = 0ull;

#pragma unroll 1
    for (int k0 = 0; k0 < F; k0 += 4) {
        float4 xv[4];
#pragma unroll
        for (int r = 0; r < 4; r++)
            xv[r] = *(float4*)&Xs[(ty * 4 + r) * F + k0];
#pragma unroll
        for (int kk = 0; kk < 4; kk++) {
            const float* wrow = &Ws[(k0 + kk) * F + tx * 8];
            ulonglong2 wa = *(const ulonglong2*)wrow;        // pairs 0,1
            ulonglong2 wb = *(const ulonglong2*)(wrow + 4);  // pairs 2,3
            float xs0 = (kk == 0) ? xv[0].x : (kk == 1) ? xv[0].y : (kk == 2) ? xv[0].z : xv[0].w;
            float xs1 = (kk == 0) ? xv[1].x : (kk == 1) ? xv[1].y : (kk == 2) ? xv[1].z : xv[1].w;
            float xs2 = (kk == 0) ? xv[2].x : (kk == 1) ? xv[2].y : (kk == 2) ? xv[2].z : xv[2].w;
            float xs3 = (kk == 0) ? xv[3].x : (kk == 1) ? xv[3].y : (kk == 2) ? xv[3].z : xv[3].w;
            unsigned long long xp0 = pack2(xs0), xp1 = pack2(xs1);
            unsigned long long xp2 = pack2(xs2), xp3 = pack2(xs3);
            ffma2(acc[0][0], xp0, wa.x); ffma2(acc[0][1], xp0, wa.y);
            ffma2(acc[0][2], xp0, wb.x); ffma2(acc[0][3], xp0, wb.y);
            ffma2(acc[1][0], xp1, wa.x); ffma2(acc[1][1], xp1, wa.y);
            ffma2(acc[1][2], xp1, wb.x); ffma2(acc[1][3], xp1, wb.y);
            ffma2(acc[2][0], xp2, wa.x); ffma2(acc[2][1], xp2, wa.y);
            ffma2(acc[2][2], xp2, wb.x); ffma2(acc[2][3], xp2, wb.y);
            ffma2(acc[3][0], xp3, wa.x); ffma2(acc[3][1], xp3, wa.y);
            ffma2(acc[3][2], xp3, wb.x); ffma2(acc[3][3], xp3, wb.y);
        }
    }

#pragma unroll
    for (int r = 0; r < 4; r++) {
        int row = row0 + ty * 4 + r;
        if (row < nrows) {
            float4 v0 = make_float4(lo32(acc[r][0]), hi32(acc[r][0]),
                                    lo32(acc[r][1]), hi32(acc[r][1]));
            float4 v1 = make_float4(lo32(acc[r][2]), hi32(acc[r][2]),
                                    lo32(acc[r][3]), hi32(acc[r][3]));
            *(float4*)&Y[row * F + tx * 8] = v0;
            *(float4*)&Y[row * F + tx * 8 + 4] = v1;
        }
    }
}

// ---------------- sparse aggregation, 128-wide (warp per node) --------------
__global__ void k_agg128(const float* __restrict__ H, float* __restrict__ O,
                         const float* __restrict__ bias)
{
    int gt = blockIdx.x * blockDim.x + threadIdx.x;
    int node = gt >> 5;
    int lane = gt & 31;
    const float4* H4 = (const float4*)H;

    float4 h = H4[node * 32 + lane];
    float ns = g_nself[node];
    float4 acc = make_float4(ns * h.x, ns * h.y, ns * h.z, ns * h.w);

    int p = g_rowptr[node];
    int p1 = g_rowptr[node + 1];
    int s = 0; float v = 0.f;
    if (p < p1) { s = g_csrc[p]; v = g_cval[p]; }
    while (p < p1) {
        int sn = 0; float vn = 0.f;
        if (p + 1 < p1) { sn = g_csrc[p + 1]; vn = g_cval[p + 1]; }
        float4 hs = H4[s * 32 + lane];
        acc.x += v * hs.x; acc.y += v * hs.y; acc.z += v * hs.z; acc.w += v * hs.w;
        s = sn; v = vn; p++;
    }
    float4 b = ((const float4*)bias)[lane];
    acc.x = fmaxf(acc.x + b.x, 0.f); acc.y = fmaxf(acc.y + b.y, 0.f);
    acc.z = fmaxf(acc.z + b.z, 0.f); acc.w = fmaxf(acc.w + b.w, 0.f);
    ((float4*)O)[node * 32 + lane] = acc;
}

// ---------------- agg2 fused with output GEMM -------------------------------
// t = relu(agg(H) + b2)  (kept in registers, 4 feats/lane), h3 = t @ W3
__global__ void k_agg_out(const float* __restrict__ H,
                          const float* __restrict__ bias,
                          const float* __restrict__ W3)
{
    __shared__ __align__(16) float Wt[OUTC * F];  // [c][k]
    int tid = threadIdx.x;
    for (int i = tid; i < OUTC * F; i += blockDim.x) {
        int c = i >> 7, k = i & 127;
        Wt[i] = W3[k * OUTC + c];
    }
    __syncthreads();

    int gt = blockIdx.x * blockDim.x + tid;
    int node = gt >> 5;
    int lane = gt & 31;
    const float4* H4 = (const float4*)H;

    float4 h = H4[node * 32 + lane];
    float ns = g_nself[node];
    float4 acc = make_float4(ns * h.x, ns * h.y, ns * h.z, ns * h.w);

    int p = g_rowptr[node];
    int p1 = g_rowptr[node + 1];
    int s = 0; float v = 0.f;
    if (p < p1) { s = g_csrc[p]; v = g_cval[p]; }
    while (p < p1) {
        int sn = 0; float vn = 0.f;
        if (p + 1 < p1) { sn = g_csrc[p + 1]; vn = g_cval[p + 1]; }
        float4 hs = H4[s * 32 + lane];
        acc.x += v * hs.x; acc.y += v * hs.y; acc.z += v * hs.z; acc.w += v * hs.w;
        s = sn; v = vn; p++;
    }
    float4 b = ((const float4*)bias)[lane];
    acc.x = fmaxf(acc.x + b.x, 0.f); acc.y = fmaxf(acc.y + b.y, 0.f);
    acc.z = fmaxf(acc.z + b.z, 0.f); acc.w = fmaxf(acc.w + b.w, 0.f);

    // h3 = t @ W3 : per-class partial dot then warp reduce
    float o[OUTC];
#pragma unroll
    for (int c = 0; c < OUTC; c++) {
        float4 wv = ((const float4*)Wt)[c * 32 + lane];
        o[c] = acc.x * wv.x + acc.y * wv.y + acc.z * wv.z + acc.w * wv.w;
    }
#pragma unroll
    for (int off = 16; off; off >>= 1)
#pragma unroll
        for (int c = 0; c < OUTC; c++)
            o[c] += __shfl_xor_sync(0xffffffffu, o[c], off);
    if (lane == 0) {
#pragma unroll
        for (int c = 0; c < OUTC; c++) g_h3[node * OUTC + c] = o[c];
    }
}

// ---------------- sparse agg 10-wide + bias + pooling (fused) ---------------
__global__ void k_agg10_pool(const float* __restrict__ b3,
                             const int* __restrict__ batch)
{
    __shared__ float sp[GG * OUTC];
    __shared__ float sc[GG];
    int tid = threadIdx.x;
    for (int j = tid; j < GG * OUTC; j += blockDim.x) sp[j] = 0.f;
    for (int j = tid; j < GG; j += blockDim.x) sc[j] = 0.f;
    __syncthreads();

    int gt = blockIdx.x * blockDim.x + tid;
    int node = gt >> 5;
    int lane = gt & 31;

    float acc = 0.f;
    if (lane < OUTC) acc = g_nself[node] * g_h3[node * OUTC + lane];
    int p = g_rowptr[node];
    int p1 = g_rowptr[node + 1];
    for (; p < p1; p++) {
        int s = g_csrc[p];
        float v = g_cval[p];
        if (lane < OUTC) acc += v * g_h3[s * OUTC + lane];
    }
    int g = batch[node];
    if (lane < OUTC) atomicAdd(&sp[g * OUTC + lane], acc + b3[lane]);
    if (lane == OUTC) atomicAdd(&sc[g], 1.0f);
    __syncthreads();

    for (int j = tid; j < GG * OUTC; j += blockDim.x)
        if (sp[j] != 0.f) atomicAdd(&g_pool[j], sp[j]);
    for (int j = tid; j < GG; j += blockDim.x)
        if (sc[j] != 0.f) atomicAdd(&g_pcnt[j], sc[j]);
}

// ---------------- mean + log_softmax ----------------------------------------
__global__ void k_final(float* __restrict__ out)
{
    int g = threadIdx.x;
    if (g >= GG) return;
    float cnt = fmaxf(g_pcnt[g], 1.0f);
    float v[OUTC];
    float m = -1e30f;
#pragma unroll
    for (int c = 0; c < OUTC; c++) {
        v[c] = g_pool[g * OUTC + c] / cnt;
        m = fmaxf(m, v[c]);
    }
    float s = 0.f;
#pragma unroll
    for (int c = 0; c < OUTC; c++) s += expf(v[c] - m);
    float l = logf(s) + m;
#pragma unroll
    for (int c = 0; c < OUTC; c++) out[g * OUTC + c] = v[c] - l;
}

// ---------------- launch ----------------------------------------------------
extern "C" void kernel_launch(void* const* d_in, const int* in_sizes, int n_in,
                              void* d_out, int out_size)
{
    const float* x     = (const float*)d_in[0];
    const int*   ei    = (const int*)  d_in[1];
    const float* ew    = (const float*)d_in[2];
    const int*   batch = (const int*)  d_in[3];
    const float* W1    = (const float*)d_in[4];
    const float* b1    = (const float*)d_in[5];
    const float* W2    = (const float*)d_in[6];
    const float* b2    = (const float*)d_in[7];
    const float* W3    = (const float*)d_in[8];
    const float* b3    = (const float*)d_in[9];
    float* out = (float*)d_out;

    const int SMEM_GEMM = (F * F + 64 * F) * sizeof(float);   // 96 KB
    cudaFuncSetAttribute(k_gemm128, cudaFuncAttributeMaxDynamicSharedMemorySize, SMEM_GEMM);

    float *h1p, *h2p;
    cudaGetSymbolAddress((void**)&h1p, g_h1);
    cudaGetSymbolAddress((void**)&h2p, g_h2);

    const int nBlkN = (NN + 255) / 256;          // 196
    const int nBlkE = (EE + 255) / 256;          // 3125
    const int nBlkW = (NN * 32) / 256;           // 6250 (warp-per-node, exact)
    const int nBlkG = (NN + 63) / 64;            // 782

    k_zero <<<nBlkN, 256>>>();                                  // 0
    k_deg  <<<nBlkE, 256>>>(ei, ew);                            // 1
    k_scan1<<<nBlkN, 256>>>();                                  // 2
    k_scan2<<<1, 256>>>(nBlkN);                                 // 3
    k_scan3<<<nBlkN, 256>>>();                                  // 4
    k_gemm128<<<nBlkG, 256, SMEM_GEMM>>>(x, W1, h1p, NN);       // 5  <- ncu sample
    k_fill <<<nBlkE, 256>>>(ei, ew);                            // 6

    k_agg128<<<nBlkW, 256>>>(h1p, h2p, b1);                     // 7
    k_gemm128<<<nBlkG, 256, SMEM_GEMM>>>(h2p, W2, h1p, NN);     // 8
    k_agg_out<<<nBlkW, 256>>>(h1p, b2, W3);                     // 9
    k_agg10_pool<<<nBlkW, 256>>>(b3, batch);                    // 10
    k_final<<<1, 64>>>(out);                                    // 11
}

// round 3
// speedup vs baseline: 1.7343x; 1.7343x over previous
#include <cuda_runtime.h>
#include <math.h>

#define NN 50000
#define EE 800000
#define F 128
#define OUTC 10
#define GG 64

// ---------------- scratch (device globals; no allocation allowed) ----------
__device__ __align__(16) float g_deg[NN];
__device__ __align__(16) float g_dinv[NN];
__device__ __align__(16) float g_nself[NN];
__device__ __align__(16) int   g_cnt[NN];
__device__ __align__(16) int   g_fill[NN];
__device__ __align__(16) int   g_rowptr[NN + 1];
__device__ __align__(16) int   g_csrc[EE];
__device__ __align__(16) float g_cval[EE];
__device__ __align__(16) float g_h1[NN * F];
__device__ __align__(16) float g_h2[NN * F];
__device__ __align__(16) float g_h3[NN * OUTC];
__device__ __align__(16) float g_pool[GG * OUTC];
__device__ __align__(16) float g_pcnt[GG];
__device__ __align__(16) int   g_bsum[256];

// ---------------- init ------------------------------------------------------
__global__ void k_zero() {
    int i = blockIdx.x * blockDim.x + threadIdx.x;
    if (i < NN) { g_deg[i] = 0.f; g_cnt[i] = 0; g_fill[i] = 0; }
    if (i < GG * OUTC) g_pool[i] = 0.f;
    if (i < GG) g_pcnt[i] = 0.f;
}

// degree (weighted, by dst) + in-degree histogram
__global__ void k_deg(const int* __restrict__ ei, const float* __restrict__ ew) {
    int e = blockIdx.x * blockDim.x + threadIdx.x;
    if (e >= EE) return;
    int d = ei[EE + e];
    atomicAdd(&g_deg[d], ew[e]);
    atomicAdd(&g_cnt[d], 1);
}

// fused: dinv + per-block exclusive scan of cnt
__global__ void k_scan1() {
    __shared__ int s[256];
    int tid = threadIdx.x;
    int i = blockIdx.x * 256 + tid;
    if (i < NN) {
        float di = rsqrtf(g_deg[i] + 1.0f);
        g_dinv[i] = di;
        g_nself[i] = di * di;
    }
    int v = (i < NN) ? g_cnt[i] : 0;
    s[tid] = v; __syncthreads();
#pragma unroll
    for (int off = 1; off < 256; off <<= 1) {
        int t = (tid >= off) ? s[tid - off] : 0;
        __syncthreads();
        s[tid] += t;
        __syncthreads();
    }
    if (i < NN) g_rowptr[i] = s[tid] - v;
    if (tid == 255) g_bsum[blockIdx.x] = s[255];
}

__global__ void k_scan2(int nblk) {
    __shared__ int s[256];
    int tid = threadIdx.x;
    int v = (tid < nblk) ? g_bsum[tid] : 0;
    s[tid] = v; __syncthreads();
#pragma unroll
    for (int off = 1; off < 256; off <<= 1) {
        int t = (tid >= off) ? s[tid - off] : 0;
        __syncthreads();
        s[tid] += t;
        __syncthreads();
    }
    if (tid < nblk) g_bsum[tid] = s[tid] - v;
}

__global__ void k_scan3() {
    int i = blockIdx.x * blockDim.x + threadIdx.x;
    if (i < NN) g_rowptr[i] += g_bsum[i >> 8];
    if (i == 0) g_rowptr[NN] = EE;
}

// scatter edges into per-dst buckets, storing src + norm value
__global__ void k_fill(const int* __restrict__ ei, const float* __restrict__ ew) {
    int e = blockIdx.x * blockDim.x + threadIdx.x;
    if (e >= EE) return;
    int s = ei[e];
    int d = ei[EE + e];
    float nv = g_dinv[s] * ew[e] * g_dinv[d];
    int p = g_rowptr[d] + atomicAdd(&g_fill[d], 1);
    g_csrc[p] = s;
    g_cval[p] = nv;
}

// ---------------- dense GEMM: Y[nr,128] = X[nr,128] @ W[128,128] ------------
// (reverted to R1 proven version: 256 thr, 64x128 tile, thread = 8 rows x 4 cols)
__global__ void __launch_bounds__(256) k_gemm128(
    const float* __restrict__ X, const float* __restrict__ W,
    float* __restrict__ Y, int nrows)
{
    extern __shared__ float smem[];
    float* Ws = smem;              // 128*128
    float* Xs = smem + F * F;      // 64*128
    int tid = threadIdx.x;
    for (int i = tid * 4; i < F * F; i += 1024)
        *(float4*)&Ws[i] = *(const float4*)&W[i];
    int row0 = blockIdx.x * 64;
    for (int i = tid * 4; i < 64 * F; i += 1024) {
        int r = row0 + (i >> 7);
        float4 v = make_float4(0.f, 0.f, 0.f, 0.f);
        if (r < nrows) v = *(const float4*)&X[r * F + (i & 127)];
        *(float4*)&Xs[i] = v;
    }
    __syncthreads();

    int tx = tid & 31;   // 4 cols at tx*4
    int ty = tid >> 5;   // 8 rows at ty*8
    float acc[8][4];
#pragma unroll
    for (int r = 0; r < 8; r++)
#pragma unroll
        for (int c = 0; c < 4; c++) acc[r][c] = 0.f;

#pragma unroll 1
    for (int k = 0; k < F; k += 4) {
        float4 xv[8];
#pragma unroll
        for (int r = 0; r < 8; r++)
            xv[r] = *(float4*)&Xs[(ty * 8 + r) * F + k];
        float4 wv[4];
#pragma unroll
        for (int kk = 0; kk < 4; kk++)
            wv[kk] = *(float4*)&Ws[(k + kk) * F + tx * 4];
#pragma unroll
        for (int r = 0; r < 8; r++) {
            acc[r][0] += xv[r].x * wv[0].x + xv[r].y * wv[1].x + xv[r].z * wv[2].x + xv[r].w * wv[3].x;
            acc[r][1] += xv[r].x * wv[0].y + xv[r].y * wv[1].y + xv[r].z * wv[2].y + xv[r].w * wv[3].y;
            acc[r][2] += xv[r].x * wv[0].z + xv[r].y * wv[1].z + xv[r].z * wv[2].z + xv[r].w * wv[3].z;
            acc[r][3] += xv[r].x * wv[0].w + xv[r].y * wv[1].w + xv[r].z * wv[2].w + xv[r].w * wv[3].w;
        }
    }

#pragma unroll
    for (int r = 0; r < 8; r++) {
        int row = row0 + ty * 8 + r;
        if (row < nrows) {
            float4 v = make_float4(acc[r][0], acc[r][1], acc[r][2], acc[r][3]);
            *(float4*)&Y[row * F + tx * 4] = v;
        }
    }
}

// ---------------- sparse aggregation, 128-wide (warp per node) --------------
__global__ void k_agg128(const float* __restrict__ H, float* __restrict__ O,
                         const float* __restrict__ bias)
{
    int gt = blockIdx.x * blockDim.x + threadIdx.x;
    int node = gt >> 5;
    int lane = gt & 31;
    const float4* H4 = (const float4*)H;

    float4 h = H4[node * 32 + lane];
    float ns = g_nself[node];
    float4 acc = make_float4(ns * h.x, ns * h.y, ns * h.z, ns * h.w);

    int p = g_rowptr[node];
    int p1 = g_rowptr[node + 1];
    int s = 0; float v = 0.f;
    if (p < p1) { s = g_csrc[p]; v = g_cval[p]; }
    while (p < p1) {
        int sn = 0; float vn = 0.f;
        if (p + 1 < p1) { sn = g_csrc[p + 1]; vn = g_cval[p + 1]; }
        float4 hs = H4[s * 32 + lane];
        acc.x += v * hs.x; acc.y += v * hs.y; acc.z += v * hs.z; acc.w += v * hs.w;
        s = sn; v = vn; p++;
    }
    float4 b = ((const float4*)bias)[lane];
    acc.x = fmaxf(acc.x + b.x, 0.f); acc.y = fmaxf(acc.y + b.y, 0.f);
    acc.z = fmaxf(acc.z + b.z, 0.f); acc.w = fmaxf(acc.w + b.w, 0.f);
    ((float4*)O)[node * 32 + lane] = acc;
}

// ---------------- agg2 fused with output GEMM -------------------------------
// t = relu(agg(H) + b2)  (kept in registers, 4 feats/lane), h3 = t @ W3
__global__ void k_agg_out(const float* __restrict__ H,
                          const float* __restrict__ bias,
                          const float* __restrict__ W3)
{
    __shared__ __align__(16) float Wt[OUTC * F];  // [c][k]
    int tid = threadIdx.x;
    for (int i = tid; i < OUTC * F; i += blockDim.x) {
        int c = i >> 7, k = i & 127;
        Wt[i] = W3[k * OUTC + c];
    }
    __syncthreads();

    int gt = blockIdx.x * blockDim.x + tid;
    int node = gt >> 5;
    int lane = gt & 31;
    const float4* H4 = (const float4*)H;

    float4 h = H4[node * 32 + lane];
    float ns = g_nself[node];
    float4 acc = make_float4(ns * h.x, ns * h.y, ns * h.z, ns * h.w);

    int p = g_rowptr[node];
    int p1 = g_rowptr[node + 1];
    int s = 0; float v = 0.f;
    if (p < p1) { s = g_csrc[p]; v = g_cval[p]; }
    while (p < p1) {
        int sn = 0; float vn = 0.f;
        if (p + 1 < p1) { sn = g_csrc[p + 1]; vn = g_cval[p + 1]; }
        float4 hs = H4[s * 32 + lane];
        acc.x += v * hs.x; acc.y += v * hs.y; acc.z += v * hs.z; acc.w += v * hs.w;
        s = sn; v = vn; p++;
    }
    float4 b = ((const float4*)bias)[lane];
    acc.x = fmaxf(acc.x + b.x, 0.f); acc.y = fmaxf(acc.y + b.y, 0.f);
    acc.z = fmaxf(acc.z + b.z, 0.f); acc.w = fmaxf(acc.w + b.w, 0.f);

    // h3 = t @ W3 : per-class partial dot then warp reduce
    float o[OUTC];
#pragma unroll
    for (int c = 0; c < OUTC; c++) {
        float4 wv = ((const float4*)Wt)[c * 32 + lane];
        o[c] = acc.x * wv.x + acc.y * wv.y + acc.z * wv.z + acc.w * wv.w;
    }
#pragma unroll
    for (int off = 16; off; off >>= 1)
#pragma unroll
        for (int c = 0; c < OUTC; c++)
            o[c] += __shfl_xor_sync(0xffffffffu, o[c], off);
    if (lane == 0) {
#pragma unroll
        for (int c = 0; c < OUTC; c++) g_h3[node * OUTC + c] = o[c];
    }
}

// ---------------- sparse agg 10-wide + bias + pooling (fused) ---------------
__global__ void k_agg10_pool(const float* __restrict__ b3,
                             const int* __restrict__ batch)
{
    __shared__ float sp[GG * OUTC];
    __shared__ float sc[GG];
    int tid = threadIdx.x;
    for (int j = tid; j < GG * OUTC; j += blockDim.x) sp[j] = 0.f;
    for (int j = tid; j < GG; j += blockDim.x) sc[j] = 0.f;
    __syncthreads();

    int gt = blockIdx.x * blockDim.x + tid;
    int node = gt >> 5;
    int lane = gt & 31;

    float acc = 0.f;
    if (lane < OUTC) acc = g_nself[node] * g_h3[node * OUTC + lane];
    int p = g_rowptr[node];
    int p1 = g_rowptr[node + 1];
    for (; p < p1; p++) {
        int s = g_csrc[p];
        float v = g_cval[p];
        if (lane < OUTC) acc += v * g_h3[s * OUTC + lane];
    }
    int g = batch[node];
    if (lane < OUTC) atomicAdd(&sp[g * OUTC + lane], acc + b3[lane]);
    if (lane == OUTC) atomicAdd(&sc[g], 1.0f);
    __syncthreads();

    for (int j = tid; j < GG * OUTC; j += blockDim.x)
        if (sp[j] != 0.f) atomicAdd(&g_pool[j], sp[j]);
    for (int j = tid; j < GG; j += blockDim.x)
        if (sc[j] != 0.f) atomicAdd(&g_pcnt[j], sc[j]);
}

// ---------------- mean + log_softmax ----------------------------------------
__global__ void k_final(float* __restrict__ out)
{
    int g = threadIdx.x;
    if (g >= GG) return;
    float cnt = fmaxf(g_pcnt[g], 1.0f);
    float v[OUTC];
    float m = -1e30f;
#pragma unroll
    for (int c = 0; c < OUTC; c++) {
        v[c] = g_pool[g * OUTC + c] / cnt;
        m = fmaxf(m, v[c]);
    }
    float s = 0.f;
#pragma unroll
    for (int c = 0; c < OUTC; c++) s += expf(v[c] - m);
    float l = logf(s) + m;
#pragma unroll
    for (int c = 0; c < OUTC; c++) out[g * OUTC + c] = v[c] - l;
}

// ---------------- launch ----------------------------------------------------
extern "C" void kernel_launch(void* const* d_in, const int* in_sizes, int n_in,
                              void* d_out, int out_size)
{
    const float* x     = (const float*)d_in[0];
    const int*   ei    = (const int*)  d_in[1];
    const float* ew    = (const float*)d_in[2];
    const int*   batch = (const int*)  d_in[3];
    const float* W1    = (const float*)d_in[4];
    const float* b1    = (const float*)d_in[5];
    const float* W2    = (const float*)d_in[6];
    const float* b2    = (const float*)d_in[7];
    const float* W3    = (const float*)d_in[8];
    const float* b3    = (const float*)d_in[9];
    float* out = (float*)d_out;

    const int SMEM_GEMM = (F * F + 64 * F) * sizeof(float);   // 96 KB
    cudaFuncSetAttribute(k_gemm128, cudaFuncAttributeMaxDynamicSharedMemorySize, SMEM_GEMM);

    float *h1p, *h2p;
    cudaGetSymbolAddress((void**)&h1p, g_h1);
    cudaGetSymbolAddress((void**)&h2p, g_h2);

    const int nBlkN = (NN + 255) / 256;          // 196
    const int nBlkE = (EE + 255) / 256;          // 3125
    const int nBlkW = (NN * 32) / 256;           // 6250 (warp-per-node, exact)
    const int nBlkG = (NN + 63) / 64;            // 782

    k_zero <<<nBlkN, 256>>>();
    k_deg  <<<nBlkE, 256>>>(ei, ew);
    k_scan1<<<nBlkN, 256>>>();
    k_scan2<<<1, 256>>>(nBlkN);
    k_scan3<<<nBlkN, 256>>>();
    k_gemm128<<<nBlkG, 256, SMEM_GEMM>>>(x, W1, h1p, NN);
    k_fill <<<nBlkE, 256>>>(ei, ew);

    k_agg128<<<nBlkW, 256>>>(h1p, h2p, b1);
    k_gemm128<<<nBlkG, 256, SMEM_GEMM>>>(h2p, W2, h1p, NN);
    k_agg_out<<<nBlkW, 256>>>(h1p, b2, W3);
    k_agg10_pool<<<nBlkW, 256>>>(b3, batch);
    k_final<<<1, 64>>>(out);
}

// round 5
// speedup vs baseline: 1.8603x; 1.0727x over previous
#include <cuda_runtime.h>
#include <cstdint>
#include <math.h>

#define NN 50000
#define EE 800000
#define F 128
#define OUTC 10
#define GG 64

#define XS_STRIDE 132   // 132 mod 32 = 4  -> A-frag LDS conflict-free
#define WS_STRIDE 136   // 136 mod 32 = 8  -> B-frag LDS conflict-free

// ---------------- scratch (device globals; no allocation allowed) ----------
__device__ __align__(16) float g_deg[NN];
__device__ __align__(16) float g_dinv[NN];
__device__ __align__(16) float g_nself[NN];
__device__ __align__(16) int   g_cnt[NN];
__device__ __align__(16) int   g_fill[NN];
__device__ __align__(16) int   g_rowptr[NN + 1];
__device__ __align__(16) int   g_csrc[EE];
__device__ __align__(16) float g_cval[EE];
__device__ __align__(16) float g_h1[NN * F];
__device__ __align__(16) float g_h2[NN * F];
__device__ __align__(16) float g_h3[NN * OUTC];
__device__ __align__(16) float g_pool[GG * OUTC];
__device__ __align__(16) float g_pcnt[GG];
__device__ __align__(16) int   g_bsum[256];

// ---------------- mma helpers -----------------------------------------------
__device__ __forceinline__ uint32_t f2tf32(float f) {
    uint32_t r;
    asm("cvt.rna.tf32.f32 %0, %1;" : "=r"(r) : "f"(f));
    return r;
}
__device__ __forceinline__ void mma_tf32(float* d, const uint32_t* a, const uint32_t* b) {
    asm volatile(
        "mma.sync.aligned.m16n8k8.row.col.f32.tf32.tf32.f32 "
        "{%0,%1,%2,%3}, {%4,%5,%6,%7}, {%8,%9}, {%0,%1,%2,%3};\n"
        : "+f"(d[0]), "+f"(d[1]), "+f"(d[2]), "+f"(d[3])
        : "r"(a[0]), "r"(a[1]), "r"(a[2]), "r"(a[3]), "r"(b[0]), "r"(b[1]));
}

// ---------------- init ------------------------------------------------------
__global__ void k_zero() {
    int i = blockIdx.x * blockDim.x + threadIdx.x;
    if (i < NN) { g_deg[i] = 0.f; g_cnt[i] = 0; g_fill[i] = 0; }
    if (i < GG * OUTC) g_pool[i] = 0.f;
    if (i < GG) g_pcnt[i] = 0.f;
}

__global__ void k_deg(const int* __restrict__ ei, const float* __restrict__ ew) {
    int e = blockIdx.x * blockDim.x + threadIdx.x;
    if (e >= EE) return;
    int d = ei[EE + e];
    atomicAdd(&g_deg[d], ew[e]);
    atomicAdd(&g_cnt[d], 1);
}

__global__ void k_scan1() {
    __shared__ int s[256];
    int tid = threadIdx.x;
    int i = blockIdx.x * 256 + tid;
    if (i < NN) {
        float di = rsqrtf(g_deg[i] + 1.0f);
        g_dinv[i] = di;
        g_nself[i] = di * di;
    }
    int v = (i < NN) ? g_cnt[i] : 0;
    s[tid] = v; __syncthreads();
#pragma unroll
    for (int off = 1; off < 256; off <<= 1) {
        int t = (tid >= off) ? s[tid - off] : 0;
        __syncthreads();
        s[tid] += t;
        __syncthreads();
    }
    if (i < NN) g_rowptr[i] = s[tid] - v;
    if (tid == 255) g_bsum[blockIdx.x] = s[255];
}

__global__ void k_scan2(int nblk) {
    __shared__ int s[256];
    int tid = threadIdx.x;
    int v = (tid < nblk) ? g_bsum[tid] : 0;
    s[tid] = v; __syncthreads();
#pragma unroll
    for (int off = 1; off < 256; off <<= 1) {
        int t = (tid >= off) ? s[tid - off] : 0;
        __syncthreads();
        s[tid] += t;
        __syncthreads();
    }
    if (tid < nblk) g_bsum[tid] = s[tid] - v;
}

__global__ void k_scan3() {
    int i = blockIdx.x * blockDim.x + threadIdx.x;
    if (i < NN) g_rowptr[i] += g_bsum[i >> 8];
    if (i == 0) g_rowptr[NN] = EE;
}

__global__ void k_fill(const int* __restrict__ ei, const float* __restrict__ ew) {
    int e = blockIdx.x * blockDim.x + threadIdx.x;
    if (e >= EE) return;
    int s = ei[e];
    int d = ei[EE + e];
    float nv = g_dinv[s] * ew[e] * g_dinv[d];
    int p = g_rowptr[d] + atomicAdd(&g_fill[d], 1);
    g_csrc[p] = s;
    g_cval[p] = nv;
}

// ---------------- tf32 mma.sync GEMM: Y[nr,128] = X[nr,128] @ W[128,128] ----
// 256 thr = 8 warps; CTA tile 128 rows; warp computes 16 rows x 128 cols.
__global__ void __launch_bounds__(256) k_gemm_mma(
    const float* __restrict__ X, const float* __restrict__ W,
    float* __restrict__ Y, int nrows)
{
    extern __shared__ float smem[];
    float* Xs = smem;                       // [128][XS_STRIDE]
    float* Ws = smem + 128 * XS_STRIDE;     // [128][WS_STRIDE]
    int tid = threadIdx.x;
    int row0 = blockIdx.x * 128;

    // stage W (tf32-converted): W[k][n] row-major
    for (int i = tid * 4; i < F * F; i += 1024) {
        int k = i >> 7, n = i & 127;
        float4 v = *(const float4*)&W[i];
        uint4 u = make_uint4(f2tf32(v.x), f2tf32(v.y), f2tf32(v.z), f2tf32(v.w));
        *(uint4*)&Ws[k * WS_STRIDE + n] = u;
    }
    // stage X tile (zero-padded)
    for (int i = tid * 4; i < 128 * F; i += 1024) {
        int r = i >> 7, c = i & 127;
        float4 v = make_float4(0.f, 0.f, 0.f, 0.f);
        if (row0 + r < nrows) v = *(const float4*)&X[(row0 + r) * F + c];
        uint4 u = make_uint4(f2tf32(v.x), f2tf32(v.y), f2tf32(v.z), f2tf32(v.w));
        *(uint4*)&Xs[r * XS_STRIDE + c] = u;
    }
    __syncthreads();

    int wid = tid >> 5, lane = tid & 31;
    int gid = lane >> 2, tig = lane & 3;
    int mrow = wid * 16;

    float acc[16][4];
#pragma unroll
    for (int nt = 0; nt < 16; nt++)
#pragma unroll
        for (int j = 0; j < 4; j++) acc[nt][j] = 0.f;

    const uint32_t* Xu = (const uint32_t*)Xs;
    const uint32_t* Wu = (const uint32_t*)Ws;

#pragma unroll
    for (int kt = 0; kt < 16; kt++) {
        int k0 = kt * 8;
        uint32_t a[4];
        a[0] = Xu[(mrow + gid)     * XS_STRIDE + k0 + tig];
        a[1] = Xu[(mrow + gid + 8) * XS_STRIDE + k0 + tig];
        a[2] = Xu[(mrow + gid)     * XS_STRIDE + k0 + tig + 4];
        a[3] = Xu[(mrow + gid + 8) * XS_STRIDE + k0 + tig + 4];
#pragma unroll
        for (int nt = 0; nt < 16; nt++) {
            uint32_t b[2];
            b[0] = Wu[(k0 + tig)     * WS_STRIDE + nt * 8 + gid];
            b[1] = Wu[(k0 + tig + 4) * WS_STRIDE + nt * 8 + gid];
            mma_tf32(acc[nt], a, b);
        }
    }

    int r0 = row0 + mrow + gid;
    int r1 = r0 + 8;
#pragma unroll
    for (int nt = 0; nt < 16; nt++) {
        int c = nt * 8 + tig * 2;
        if (r0 < nrows) *(float2*)&Y[r0 * F + c] = make_float2(acc[nt][0], acc[nt][1]);
        if (r1 < nrows) *(float2*)&Y[r1 * F + c] = make_float2(acc[nt][2], acc[nt][3]);
    }
}

// ---------------- sparse aggregation, 128-wide (warp per node) --------------
__global__ void k_agg128(const float* __restrict__ H, float* __restrict__ O,
                         const float* __restrict__ bias)
{
    int gt = blockIdx.x * blockDim.x + threadIdx.x;
    int node = gt >> 5;
    int lane = gt & 31;
    const float4* H4 = (const float4*)H;

    float4 h = H4[node * 32 + lane];
    float ns = g_nself[node];
    float4 acc = make_float4(ns * h.x, ns * h.y, ns * h.z, ns * h.w);

    int p = g_rowptr[node];
    int p1 = g_rowptr[node + 1];
    int s = 0; float v = 0.f;
    if (p < p1) { s = g_csrc[p]; v = g_cval[p]; }
    while (p < p1) {
        int sn = 0; float vn = 0.f;
        if (p + 1 < p1) { sn = g_csrc[p + 1]; vn = g_cval[p + 1]; }
        float4 hs = H4[s * 32 + lane];
        acc.x += v * hs.x; acc.y += v * hs.y; acc.z += v * hs.z; acc.w += v * hs.w;
        s = sn; v = vn; p++;
    }
    float4 b = ((const float4*)bias)[lane];
    acc.x = fmaxf(acc.x + b.x, 0.f); acc.y = fmaxf(acc.y + b.y, 0.f);
    acc.z = fmaxf(acc.z + b.z, 0.f); acc.w = fmaxf(acc.w + b.w, 0.f);
    ((float4*)O)[node * 32 + lane] = acc;
}

// ---------------- agg2 fused with output GEMM -------------------------------
__global__ void k_agg_out(const float* __restrict__ H,
                          const float* __restrict__ bias,
                          const float* __restrict__ W3)
{
    __shared__ __align__(16) float Wt[OUTC * F];  // [c][k]
    int tid = threadIdx.x;
    for (int i = tid; i < OUTC * F; i += blockDim.x) {
        int c = i >> 7, k = i & 127;
        Wt[i] = W3[k * OUTC + c];
    }
    __syncthreads();

    int gt = blockIdx.x * blockDim.x + tid;
    int node = gt >> 5;
    int lane = gt & 31;
    const float4* H4 = (const float4*)H;

    float4 h = H4[node * 32 + lane];
    float ns = g_nself[node];
    float4 acc = make_float4(ns * h.x, ns * h.y, ns * h.z, ns * h.w);

    int p = g_rowptr[node];
    int p1 = g_rowptr[node + 1];
    int s = 0; float v = 0.f;
    if (p < p1) { s = g_csrc[p]; v = g_cval[p]; }
    while (p < p1) {
        int sn = 0; float vn = 0.f;
        if (p + 1 < p1) { sn = g_csrc[p + 1]; vn = g_cval[p + 1]; }
        float4 hs = H4[s * 32 + lane];
        acc.x += v * hs.x; acc.y += v * hs.y; acc.z += v * hs.z; acc.w += v * hs.w;
        s = sn; v = vn; p++;
    }
    float4 b = ((const float4*)bias)[lane];
    acc.x = fmaxf(acc.x + b.x, 0.f); acc.y = fmaxf(acc.y + b.y, 0.f);
    acc.z = fmaxf(acc.z + b.z, 0.f); acc.w = fmaxf(acc.w + b.w, 0.f);

    float o[OUTC];
#pragma unroll
    for (int c = 0; c < OUTC; c++) {
        float4 wv = ((const float4*)Wt)[c * 32 + lane];
        o[c] = acc.x * wv.x + acc.y * wv.y + acc.z * wv.z + acc.w * wv.w;
    }
#pragma unroll
    for (int off = 16; off; off >>= 1)
#pragma unroll
        for (int c = 0; c < OUTC; c++)
            o[c] += __shfl_xor_sync(0xffffffffu, o[c], off);
    if (lane == 0) {
#pragma unroll
        for (int c = 0; c < OUTC; c++) g_h3[node * OUTC + c] = o[c];
    }
}

// ---------------- sparse agg 10-wide + bias + pooling (fused) ---------------
__global__ void k_agg10_pool(const float* __restrict__ b3,
                             const int* __restrict__ batch)
{
    __shared__ float sp[GG * OUTC];
    __shared__ float sc[GG];
    int tid = threadIdx.x;
    for (int j = tid; j < GG * OUTC; j += blockDim.x) sp[j] = 0.f;
    for (int j = tid; j < GG; j += blockDim.x) sc[j] = 0.f;
    __syncthreads();

    int gt = blockIdx.x * blockDim.x + tid;
    int node = gt >> 5;
    int lane = gt & 31;

    float acc = 0.f;
    if (lane < OUTC) acc = g_nself[node] * g_h3[node * OUTC + lane];
    int p = g_rowptr[node];
    int p1 = g_rowptr[node + 1];
    for (; p < p1; p++) {
        int s = g_csrc[p];
        float v = g_cval[p];
        if (lane < OUTC) acc += v * g_h3[s * OUTC + lane];
    }
    int g = batch[node];
    if (lane < OUTC) atomicAdd(&sp[g * OUTC + lane], acc + b3[lane]);
    if (lane == OUTC) atomicAdd(&sc[g], 1.0f);
    __syncthreads();

    for (int j = tid; j < GG * OUTC; j += blockDim.x)
        if (sp[j] != 0.f) atomicAdd(&g_pool[j], sp[j]);
    for (int j = tid; j < GG; j += blockDim.x)
        if (sc[j] != 0.f) atomicAdd(&g_pcnt[j], sc[j]);
}

// ---------------- mean + log_softmax ----------------------------------------
__global__ void k_final(float* __restrict__ out)
{
    int g = threadIdx.x;
    if (g >= GG) return;
    float cnt = fmaxf(g_pcnt[g], 1.0f);
    float v[OUTC];
    float m = -1e30f;
#pragma unroll
    for (int c = 0; c < OUTC; c++) {
        v[c] = g_pool[g * OUTC + c] / cnt;
        m = fmaxf(m, v[c]);
    }
    float s = 0.f;
#pragma unroll
    for (int c = 0; c < OUTC; c++) s += expf(v[c] - m);
    float l = logf(s) + m;
#pragma unroll
    for (int c = 0; c < OUTC; c++) out[g * OUTC + c] = v[c] - l;
}

// ---------------- launch ----------------------------------------------------
extern "C" void kernel_launch(void* const* d_in, const int* in_sizes, int n_in,
                              void* d_out, int out_size)
{
    const float* x     = (const float*)d_in[0];
    const int*   ei    = (const int*)  d_in[1];
    const float* ew    = (const float*)d_in[2];
    const int*   batch = (const int*)  d_in[3];
    const float* W1    = (const float*)d_in[4];
    const float* b1    = (const float*)d_in[5];
    const float* W2    = (const float*)d_in[6];
    const float* b2    = (const float*)d_in[7];
    const float* W3    = (const float*)d_in[8];
    const float* b3    = (const float*)d_in[9];
    float* out = (float*)d_out;

    const int SMEM_MMA = (128 * XS_STRIDE + 128 * WS_STRIDE) * sizeof(float); // 137216
    cudaFuncSetAttribute(k_gemm_mma, cudaFuncAttributeMaxDynamicSharedMemorySize, SMEM_MMA);

    float *h1p, *h2p;
    cudaGetSymbolAddress((void**)&h1p, g_h1);
    cudaGetSymbolAddress((void**)&h2p, g_h2);

    const int nBlkN = (NN + 255) / 256;          // 196
    const int nBlkE = (EE + 255) / 256;          // 3125
    const int nBlkW = (NN * 32) / 256;           // 6250
    const int nBlkT = (NN + 127) / 128;          // 391 (mma gemm)

    k_zero <<<nBlkN, 256>>>();                                   // 0
    k_deg  <<<nBlkE, 256>>>(ei, ew);                             // 1
    k_scan1<<<nBlkN, 256>>>();                                   // 2
    k_scan2<<<1, 256>>>(nBlkN);                                  // 3
    k_scan3<<<nBlkN, 256>>>();                                   // 4
    k_gemm_mma<<<nBlkT, 256, SMEM_MMA>>>(x, W1, h1p, NN);        // 5  <- ncu sample
    k_fill <<<nBlkE, 256>>>(ei, ew);                             // 6

    k_agg128<<<nBlkW, 256>>>(h1p, h2p, b1);                      // 7
    k_gemm_mma<<<nBlkT, 256, SMEM_MMA>>>(h2p, W2, h1p, NN);      // 8
    k_agg_out<<<nBlkW, 256>>>(h1p, b2, W3);                      // 9
    k_agg10_pool<<<nBlkW, 256>>>(b3, batch);                     // 10
    k_final<<<1, 64>>>(out);                                     // 11
}

// round 7
// speedup vs baseline: 2.1038x; 1.1309x over previous
#include <cuda_runtime.h>
#include <cstdint>
#include <math.h>

#define NN 50000
#define EE 800000
#define F 128
#define OUTC 10
#define GG 64

#define XS_STRIDE 132   // 132 mod 32 = 4  -> A-frag LDS conflict-free
#define WS_STRIDE 136   // 136 mod 32 = 8  -> B-frag LDS conflict-free

// ---------------- scratch (device globals; no allocation allowed) ----------
__device__ __align__(16) float g_deg[NN];
__device__ __align__(16) float g_dinv[NN];
__device__ __align__(16) float g_nself[NN];
__device__ __align__(16) int   g_cnt[NN];
__device__ __align__(16) int   g_fill[NN];
__device__ __align__(16) int   g_rowptr[NN + 1];
__device__ __align__(16) int   g_csrc[EE];
__device__ __align__(16) float g_cval[EE];
__device__ __align__(16) float g_h1[NN * F];
__device__ __align__(16) float g_h2[NN * F];
__device__ __align__(16) float g_h3[NN * OUTC];
__device__ __align__(16) float g_pool[GG * OUTC];
__device__ __align__(16) float g_pcnt[GG];
__device__ __align__(16) int   g_bsum[256];

// ---------------- mma helpers -----------------------------------------------
__device__ __forceinline__ uint32_t f2tf32(float f) {
    uint32_t r;
    asm("cvt.rna.tf32.f32 %0, %1;" : "=r"(r) : "f"(f));
    return r;
}
__device__ __forceinline__ void mma_tf32(float* d, const uint32_t* a, const uint32_t* b) {
    asm volatile(
        "mma.sync.aligned.m16n8k8.row.col.f32.tf32.tf32.f32 "
        "{%0,%1,%2,%3}, {%4,%5,%6,%7}, {%8,%9}, {%0,%1,%2,%3};\n"
        : "+f"(d[0]), "+f"(d[1]), "+f"(d[2]), "+f"(d[3])
        : "r"(a[0]), "r"(a[1]), "r"(a[2]), "r"(a[3]), "r"(b[0]), "r"(b[1]));
}

// ---------------- init ------------------------------------------------------
__global__ void k_zero() {
    int i = blockIdx.x * blockDim.x + threadIdx.x;
    if (i < NN) { g_deg[i] = 0.f; g_cnt[i] = 0; g_fill[i] = 0; }
    if (i < GG * OUTC) g_pool[i] = 0.f;
    if (i < GG) g_pcnt[i] = 0.f;
}

__global__ void k_deg(const int* __restrict__ ei, const float* __restrict__ ew) {
    int e = blockIdx.x * blockDim.x + threadIdx.x;
    if (e >= EE) return;
    int d = ei[EE + e];
    atomicAdd(&g_deg[d], ew[e]);
    atomicAdd(&g_cnt[d], 1);
}

__global__ void k_scan1() {
    __shared__ int s[256];
    int tid = threadIdx.x;
    int i = blockIdx.x * 256 + tid;
    if (i < NN) {
        float di = rsqrtf(g_deg[i] + 1.0f);
        g_dinv[i] = di;
        g_nself[i] = di * di;
    }
    int v = (i < NN) ? g_cnt[i] : 0;
    s[tid] = v; __syncthreads();
#pragma unroll
    for (int off = 1; off < 256; off <<= 1) {
        int t = (tid >= off) ? s[tid - off] : 0;
        __syncthreads();
        s[tid] += t;
        __syncthreads();
    }
    if (i < NN) g_rowptr[i] = s[tid] - v;
    if (tid == 255) g_bsum[blockIdx.x] = s[255];
}

// fused scan2+scan3: each block reduces block-sums below it, adds to its chunk
__global__ void k_scan23() {
    __shared__ int wsum[8];
    int tid = threadIdx.x, bid = blockIdx.x;
    int lane = tid & 31, wid = tid >> 5;
    int v = (tid < bid) ? g_bsum[tid] : 0;
#pragma unroll
    for (int off = 16; off; off >>= 1) v += __shfl_xor_sync(0xffffffffu, v, off);
    if (lane == 0) wsum[wid] = v;
    __syncthreads();
    if (tid == 0) {
        int t = 0;
#pragma unroll
        for (int j = 0; j < 8; j++) t += wsum[j];
        wsum[0] = t;
    }
    __syncthreads();
    int pref = wsum[0];
    int i = bid * 256 + tid;
    if (i < NN) g_rowptr[i] += pref;
    if (i == 0) g_rowptr[NN] = EE;
}

__global__ void k_fill(const int* __restrict__ ei, const float* __restrict__ ew) {
    int e = blockIdx.x * blockDim.x + threadIdx.x;
    if (e >= EE) return;
    int s = ei[e];
    int d = ei[EE + e];
    float nv = g_dinv[s] * ew[e] * g_dinv[d];
    int p = g_rowptr[d] + atomicAdd(&g_fill[d], 1);
    g_csrc[p] = s;
    g_cval[p] = nv;
}

// ---------------- tf32 mma.sync GEMM: Y[nr,128] = X[nr,128] @ W[128,128] ----
// 256 thr = 8 warps; CTA tile 64 rows; warp = 16 rows x 64 cols (2 CTA/SM)
__global__ void __launch_bounds__(256) k_gemm_mma(
    const float* __restrict__ X, const float* __restrict__ W,
    float* __restrict__ Y, int nrows)
{
    extern __shared__ float smem[];
    float* Xs = smem;                       // [64][XS_STRIDE]
    float* Ws = smem + 64 * XS_STRIDE;      // [128][WS_STRIDE]
    int tid = threadIdx.x;
    int row0 = blockIdx.x * 64;

    // stage W (tf32-converted): W[k][n] row-major
    for (int i = tid * 4; i < F * F; i += 1024) {
        int k = i >> 7, n = i & 127;
        float4 v = *(const float4*)&W[i];
        uint4 u = make_uint4(f2tf32(v.x), f2tf32(v.y), f2tf32(v.z), f2tf32(v.w));
        *(uint4*)&Ws[k * WS_STRIDE + n] = u;
    }
    // stage X tile (zero-padded)
    for (int i = tid * 4; i < 64 * F; i += 1024) {
        int r = i >> 7, c = i & 127;
        float4 v = make_float4(0.f, 0.f, 0.f, 0.f);
        if (row0 + r < nrows) v = *(const float4*)&X[(row0 + r) * F + c];
        uint4 u = make_uint4(f2tf32(v.x), f2tf32(v.y), f2tf32(v.z), f2tf32(v.w));
        *(uint4*)&Xs[r * XS_STRIDE + c] = u;
    }
    __syncthreads();

    int wid = tid >> 5, lane = tid & 31;
    int gid = lane >> 2, tig = lane & 3;
    int mrow = (wid >> 1) * 16;       // 4 row groups
    int ncol0 = (wid & 1) * 64;       // 2 col groups

    float acc[8][4];
#pragma unroll
    for (int nt = 0; nt < 8; nt++)
#pragma unroll
        for (int j = 0; j < 4; j++) acc[nt][j] = 0.f;

    const uint32_t* Xu = (const uint32_t*)Xs;
    const uint32_t* Wu = (const uint32_t*)Ws;

#pragma unroll
    for (int kt = 0; kt < 16; kt++) {
        int k0 = kt * 8;
        uint32_t a[4];
        a[0] = Xu[(mrow + gid)     * XS_STRIDE + k0 + tig];
        a[1] = Xu[(mrow + gid + 8) * XS_STRIDE + k0 + tig];
        a[2] = Xu[(mrow + gid)     * XS_STRIDE + k0 + tig + 4];
        a[3] = Xu[(mrow + gid + 8) * XS_STRIDE + k0 + tig + 4];
#pragma unroll
        for (int nt = 0; nt < 8; nt++) {
            uint32_t b[2];
            b[0] = Wu[(k0 + tig)     * WS_STRIDE + ncol0 + nt * 8 + gid];
            b[1] = Wu[(k0 + tig + 4) * WS_STRIDE + ncol0 + nt * 8 + gid];
            mma_tf32(acc[nt], a, b);
        }
    }

    int r0 = row0 + mrow + gid;
    int r1 = r0 + 8;
#pragma unroll
    for (int nt = 0; nt < 8; nt++) {
        int c = ncol0 + nt * 8 + tig * 2;
        if (r0 < nrows) *(float2*)&Y[r0 * F + c] = make_float2(acc[nt][0], acc[nt][1]);
        if (r1 < nrows) *(float2*)&Y[r1 * F + c] = make_float2(acc[nt][2], acc[nt][3]);
    }
}

// ---------------- sparse aggregation, 128-wide (warp per node) --------------
__global__ void k_agg128(const float* __restrict__ H, float* __restrict__ O,
                         const float* __restrict__ bias)
{
    int gt = blockIdx.x * blockDim.x + threadIdx.x;
    int node = gt >> 5;
    int lane = gt & 31;
    const float4* H4 = (const float4*)H;

    float4 h = H4[node * 32 + lane];
    float ns = g_nself[node];
    float4 acc = make_float4(ns * h.x, ns * h.y, ns * h.z, ns * h.w);

    int p = g_rowptr[node];
    int p1 = g_rowptr[node + 1];
    int s = 0; float v = 0.f;
    if (p < p1) { s = g_csrc[p]; v = g_cval[p]; }
    while (p < p1) {
        int sn = 0; float vn = 0.f;
        if (p + 1 < p1) { sn = g_csrc[p + 1]; vn = g_cval[p + 1]; }
        float4 hs = H4[s * 32 + lane];
        acc.x += v * hs.x; acc.y += v * hs.y; acc.z += v * hs.z; acc.w += v * hs.w;
        s = sn; v = vn; p++;
    }
    float4 b = ((const float4*)bias)[lane];
    acc.x = fmaxf(acc.x + b.x, 0.f); acc.y = fmaxf(acc.y + b.y, 0.f);
    acc.z = fmaxf(acc.z + b.z, 0.f); acc.w = fmaxf(acc.w + b.w, 0.f);
    ((float4*)O)[node * 32 + lane] = acc;
}

// ---------------- agg2 fused with output GEMM -------------------------------
__global__ void k_agg_out(const float* __restrict__ H,
                          const float* __restrict__ bias,
                          const float* __restrict__ W3)
{
    __shared__ __align__(16) float Wt[OUTC * F];  // [c][k]
    int tid = threadIdx.x;
    for (int i = tid; i < OUTC * F; i += blockDim.x) {
        int c = i >> 7, k = i & 127;
        Wt[i] = W3[k * OUTC + c];
    }
    __syncthreads();

    int gt = blockIdx.x * blockDim.x + tid;
    int node = gt >> 5;
    int lane = gt & 31;
    const float4* H4 = (const float4*)H;

    float4 h = H4[node * 32 + lane];
    float ns = g_nself[node];
    float4 acc = make_float4(ns * h.x, ns * h.y, ns * h.z, ns * h.w);

    int p = g_rowptr[node];
    int p1 = g_rowptr[node + 1];
    int s = 0; float v = 0.f;
    if (p < p1) { s = g_csrc[p]; v = g_cval[p]; }
    while (p < p1) {
        int sn = 0; float vn = 0.f;
        if (p + 1 < p1) { sn = g_csrc[p + 1]; vn = g_cval[p + 1]; }
        float4 hs = H4[s * 32 + lane];
        acc.x += v * hs.x; acc.y += v * hs.y; acc.z += v * hs.z; acc.w += v * hs.w;
        s = sn; v = vn; p++;
    }
    float4 b = ((const float4*)bias)[lane];
    acc.x = fmaxf(acc.x + b.x, 0.f); acc.y = fmaxf(acc.y + b.y, 0.f);
    acc.z = fmaxf(acc.z + b.z, 0.f); acc.w = fmaxf(acc.w + b.w, 0.f);

    float o[OUTC];
#pragma unroll
    for (int c = 0; c < OUTC; c++) {
        float4 wv = ((const float4*)Wt)[c * 32 + lane];
        o[c] = acc.x * wv.x + acc.y * wv.y + acc.z * wv.z + acc.w * wv.w;
    }
#pragma unroll
    for (int off = 16; off; off >>= 1)
#pragma unroll
        for (int c = 0; c < OUTC; c++)
            o[c] += __shfl_xor_sync(0xffffffffu, o[c], off);
    if (lane == 0) {
#pragma unroll
        for (int c = 0; c < OUTC; c++) g_h3[node * OUTC + c] = o[c];
    }
}

// ---------------- sparse agg 10-wide + bias + pooling (fused) ---------------
__global__ void k_agg10_pool(const float* __restrict__ b3,
                             const int* __restrict__ batch)
{
    __shared__ float sp[GG * OUTC];
    __shared__ float sc[GG];
    int tid = threadIdx.x;
    for (int j = tid; j < GG * OUTC; j += blockDim.x) sp[j] = 0.f;
    for (int j = tid; j < GG; j += blockDim.x) sc[j] = 0.f;
    __syncthreads();

    int gt = blockIdx.x * blockDim.x + tid;
    int node = gt >> 5;
    int lane = gt & 31;

    float acc = 0.f;
    if (lane < OUTC) acc = g_nself[node] * g_h3[node * OUTC + lane];
    int p = g_rowptr[node];
    int p1 = g_rowptr[node + 1];
    for (; p < p1; p++) {
        int s = g_csrc[p];
        float v = g_cval[p];
        if (lane < OUTC) acc += v * g_h3[s * OUTC + lane];
    }
    int g = batch[node];
    if (lane < OUTC) atomicAdd(&sp[g * OUTC + lane], acc + b3[lane]);
    if (lane == OUTC) atomicAdd(&sc[g], 1.0f);
    __syncthreads();

    for (int j = tid; j < GG * OUTC; j += blockDim.x)
        if (sp[j] != 0.f) atomicAdd(&g_pool[j], sp[j]);
    for (int j = tid; j < GG; j += blockDim.x)
        if (sc[j] != 0.f) atomicAdd(&g_pcnt[j], sc[j]);
}

// ---------------- mean + log_softmax ----------------------------------------
__global__ void k_final(float* __restrict__ out)
{
    int g = threadIdx.x;
    if (g >= GG) return;
    float cnt = fmaxf(g_pcnt[g], 1.0f);
    float v[OUTC];
    float m = -1e30f;
#pragma unroll
    for (int c = 0; c < OUTC; c++) {
        v[c] = g_pool[g * OUTC + c] / cnt;
        m = fmaxf(m, v[c]);
    }
    float s = 0.f;
#pragma unroll
    for (int c = 0; c < OUTC; c++) s += expf(v[c] - m);
    float l = logf(s) + m;
#pragma unroll
    for (int c = 0; c < OUTC; c++) out[g * OUTC + c] = v[c] - l;
}

// ---------------- launch ----------------------------------------------------
extern "C" void kernel_launch(void* const* d_in, const int* in_sizes, int n_in,
                              void* d_out, int out_size)
{
    const float* x     = (const float*)d_in[0];
    const int*   ei    = (const int*)  d_in[1];
    const float* ew    = (const float*)d_in[2];
    const int*   batch = (const int*)  d_in[3];
    const float* W1    = (const float*)d_in[4];
    const float* b1    = (const float*)d_in[5];
    const float* W2    = (const float*)d_in[6];
    const float* b2    = (const float*)d_in[7];
    const float* W3    = (const float*)d_in[8];
    const float* b3    = (const float*)d_in[9];
    float* out = (float*)d_out;

    const int SMEM_MMA = (64 * XS_STRIDE + 128 * WS_STRIDE) * sizeof(float); // 103424
    cudaFuncSetAttribute(k_gemm_mma, cudaFuncAttributeMaxDynamicSharedMemorySize, SMEM_MMA);

    float *h1p, *h2p;
    cudaGetSymbolAddress((void**)&h1p, g_h1);
    cudaGetSymbolAddress((void**)&h2p, g_h2);

    const int nBlkN = (NN + 255) / 256;          // 196
    const int nBlkE = (EE + 255) / 256;          // 3125
    const int nBlkW = (NN * 32) / 256;           // 6250
    const int nBlkT = (NN + 63) / 64;            // 782 (mma gemm)

    k_zero <<<nBlkN, 256>>>();                                   // my 1
    k_deg  <<<nBlkE, 256>>>(ei, ew);                             // my 2
    k_scan1<<<nBlkN, 256>>>();                                   // my 3
    k_gemm_mma<<<nBlkT, 256, SMEM_MMA>>>(x, W1, h1p, NN);        // my 4 <- ncu sample (6th overall)
    k_scan23<<<nBlkN, 256>>>();                                  // my 5
    k_fill <<<nBlkE, 256>>>(ei, ew);                             // my 6

    k_agg128<<<nBlkW, 256>>>(h1p, h2p, b1);                      // my 7
    k_gemm_mma<<<nBlkT, 256, SMEM_MMA>>>(h2p, W2, h1p, NN);      // my 8
    k_agg_out<<<nBlkW, 256>>>(h1p, b2, W3);                      // my 9
    k_agg10_pool<<<nBlkW, 256>>>(b3, batch);                     // my 10
    k_final<<<1, 64>>>(out);                                     // my 11
}

// round 8
// speedup vs baseline: 2.1277x; 1.0114x over previous
#include <cuda_runtime.h>
#include <cstdint>
#include <math.h>

#define NN 50000
#define EE 800000
#define F 128
#define OUTC 10
#define GG 64

#define XS_STRIDE 132   // 132 mod 32 = 4  -> A-frag LDS conflict-free
#define WS_STRIDE 72    // 72 mod 32 = 8   -> B-frag LDS conflict-free

// ---------------- scratch (device globals; no allocation allowed) ----------
__device__ __align__(16) float g_deg[NN];
__device__ __align__(16) float g_dinv[NN];
__device__ __align__(16) float g_nself[NN];
__device__ __align__(16) int   g_cnt[NN];
__device__ __align__(16) int   g_fill[NN];
__device__ __align__(16) int   g_rowptr[NN + 1];
__device__ __align__(16) int   g_csrc[EE];
__device__ __align__(16) float g_cval[EE];
__device__ __align__(16) float g_h1[NN * F];
__device__ __align__(16) float g_h2[NN * F];
__device__ __align__(16) float g_h3[NN * OUTC];
__device__ __align__(16) float g_pool[GG * OUTC];
__device__ __align__(16) float g_pcnt[GG];
__device__ __align__(16) int   g_bsum[256];

// ---------------- mma helpers -----------------------------------------------
__device__ __forceinline__ uint32_t f2tf32(float f) {
    uint32_t r;
    asm("cvt.rna.tf32.f32 %0, %1;" : "=r"(r) : "f"(f));
    return r;
}
__device__ __forceinline__ void mma_tf32(float* d, const uint32_t* a, const uint32_t* b) {
    asm volatile(
        "mma.sync.aligned.m16n8k8.row.col.f32.tf32.tf32.f32 "
        "{%0,%1,%2,%3}, {%4,%5,%6,%7}, {%8,%9}, {%0,%1,%2,%3};\n"
        : "+f"(d[0]), "+f"(d[1]), "+f"(d[2]), "+f"(d[3])
        : "r"(a[0]), "r"(a[1]), "r"(a[2]), "r"(a[3]), "r"(b[0]), "r"(b[1]));
}

// ---------------- init ------------------------------------------------------
__global__ void k_zero() {
    int i = blockIdx.x * blockDim.x + threadIdx.x;
    if (i < NN) { g_deg[i] = 0.f; g_cnt[i] = 0; g_fill[i] = 0; }
    if (i < GG * OUTC) g_pool[i] = 0.f;
    if (i < GG) g_pcnt[i] = 0.f;
}

__global__ void k_deg(const int* __restrict__ ei, const float* __restrict__ ew) {
    int e = blockIdx.x * blockDim.x + threadIdx.x;
    if (e >= EE) return;
    int d = ei[EE + e];
    atomicAdd(&g_deg[d], ew[e]);
    atomicAdd(&g_cnt[d], 1);
}

__global__ void k_scan1() {
    __shared__ int s[256];
    int tid = threadIdx.x;
    int i = blockIdx.x * 256 + tid;
    if (i < NN) {
        float di = rsqrtf(g_deg[i] + 1.0f);
        g_dinv[i] = di;
        g_nself[i] = di * di;
    }
    int v = (i < NN) ? g_cnt[i] : 0;
    s[tid] = v; __syncthreads();
#pragma unroll
    for (int off = 1; off < 256; off <<= 1) {
        int t = (tid >= off) ? s[tid - off] : 0;
        __syncthreads();
        s[tid] += t;
        __syncthreads();
    }
    if (i < NN) g_rowptr[i] = s[tid] - v;
    if (tid == 255) g_bsum[blockIdx.x] = s[255];
}

// fused scan2+scan3
__global__ void k_scan23() {
    __shared__ int wsum[8];
    int tid = threadIdx.x, bid = blockIdx.x;
    int lane = tid & 31, wid = tid >> 5;
    int v = (tid < bid) ? g_bsum[tid] : 0;
#pragma unroll
    for (int off = 16; off; off >>= 1) v += __shfl_xor_sync(0xffffffffu, v, off);
    if (lane == 0) wsum[wid] = v;
    __syncthreads();
    if (tid == 0) {
        int t = 0;
#pragma unroll
        for (int j = 0; j < 8; j++) t += wsum[j];
        wsum[0] = t;
    }
    __syncthreads();
    int pref = wsum[0];
    int i = bid * 256 + tid;
    if (i < NN) g_rowptr[i] += pref;
    if (i == 0) g_rowptr[NN] = EE;
}

__global__ void k_fill(const int* __restrict__ ei, const float* __restrict__ ew) {
    int e = blockIdx.x * blockDim.x + threadIdx.x;
    if (e >= EE) return;
    int s = ei[e];
    int d = ei[EE + e];
    float nv = g_dinv[s] * ew[e] * g_dinv[d];
    int p = g_rowptr[d] + atomicAdd(&g_fill[d], 1);
    g_csrc[p] = s;
    g_cval[p] = nv;
}

// ---------------- tf32 mma.sync GEMM, N-split -------------------------------
// CTA = 64 rows x 64 cols; 8 warps = 4 row-groups x 2 col-groups, warp 16x32.
// grid 1D: n0 = (bid & 1)*64, row0 = (bid >> 1)*64. 3 CTA/SM (70.7 KB smem).
__global__ void __launch_bounds__(256) k_gemm_mma(
    const float* __restrict__ X, const float* __restrict__ W,
    float* __restrict__ Y, int nrows)
{
    extern __shared__ float smem[];
    float* Xs = smem;                       // [64][XS_STRIDE]
    float* Ws = smem + 64 * XS_STRIDE;      // [128][WS_STRIDE] (64-col slice)
    int tid = threadIdx.x;
    int row0 = (blockIdx.x >> 1) * 64;
    int n0   = (blockIdx.x & 1) * 64;

    // stage W col-slice (tf32-converted): Ws[k][n] = W[k][n0+n]
    for (int i = tid * 4; i < F * 64; i += 1024) {
        int k = i >> 6, n = i & 63;
        float4 v = *(const float4*)&W[k * F + n0 + n];
        uint4 u = make_uint4(f2tf32(v.x), f2tf32(v.y), f2tf32(v.z), f2tf32(v.w));
        *(uint4*)&Ws[k * WS_STRIDE + n] = u;
    }
    // stage X tile (zero-padded)
    for (int i = tid * 4; i < 64 * F; i += 1024) {
        int r = i >> 7, c = i & 127;
        float4 v = make_float4(0.f, 0.f, 0.f, 0.f);
        if (row0 + r < nrows) v = *(const float4*)&X[(row0 + r) * F + c];
        uint4 u = make_uint4(f2tf32(v.x), f2tf32(v.y), f2tf32(v.z), f2tf32(v.w));
        *(uint4*)&Xs[r * XS_STRIDE + c] = u;
    }
    __syncthreads();

    int wid = tid >> 5, lane = tid & 31;
    int gid = lane >> 2, tig = lane & 3;
    int mrow = (wid >> 1) * 16;       // 4 row groups of 16
    int ncol0 = (wid & 1) * 32;       // 2 col groups of 32

    float acc[4][4];
#pragma unroll
    for (int nt = 0; nt < 4; nt++)
#pragma unroll
        for (int j = 0; j < 4; j++) acc[nt][j] = 0.f;

    const uint32_t* Xu = (const uint32_t*)Xs;
    const uint32_t* Wu = (const uint32_t*)Ws;

#pragma unroll
    for (int kt = 0; kt < 16; kt++) {
        int k0 = kt * 8;
        uint32_t a[4];
        a[0] = Xu[(mrow + gid)     * XS_STRIDE + k0 + tig];
        a[1] = Xu[(mrow + gid + 8) * XS_STRIDE + k0 + tig];
        a[2] = Xu[(mrow + gid)     * XS_STRIDE + k0 + tig + 4];
        a[3] = Xu[(mrow + gid + 8) * XS_STRIDE + k0 + tig + 4];
#pragma unroll
        for (int nt = 0; nt < 4; nt++) {
            uint32_t b[2];
            b[0] = Wu[(k0 + tig)     * WS_STRIDE + ncol0 + nt * 8 + gid];
            b[1] = Wu[(k0 + tig + 4) * WS_STRIDE + ncol0 + nt * 8 + gid];
            mma_tf32(acc[nt], a, b);
        }
    }

    int r0 = row0 + mrow + gid;
    int r1 = r0 + 8;
#pragma unroll
    for (int nt = 0; nt < 4; nt++) {
        int c = n0 + ncol0 + nt * 8 + tig * 2;
        if (r0 < nrows) *(float2*)&Y[r0 * F + c] = make_float2(acc[nt][0], acc[nt][1]);
        if (r1 < nrows) *(float2*)&Y[r1 * F + c] = make_float2(acc[nt][2], acc[nt][3]);
    }
}

// ---------------- sparse aggregation, 128-wide (warp per node) --------------
__global__ void k_agg128(const float* __restrict__ H, float* __restrict__ O,
                         const float* __restrict__ bias)
{
    int gt = blockIdx.x * blockDim.x + threadIdx.x;
    int node = gt >> 5;
    int lane = gt & 31;
    const float4* H4 = (const float4*)H;

    float4 h = H4[node * 32 + lane];
    float ns = g_nself[node];
    float4 acc = make_float4(ns * h.x, ns * h.y, ns * h.z, ns * h.w);

    int p = g_rowptr[node];
    int p1 = g_rowptr[node + 1];
    int s = 0; float v = 0.f;
    if (p < p1) { s = g_csrc[p]; v = g_cval[p]; }
    while (p < p1) {
        int sn = 0; float vn = 0.f;
        if (p + 1 < p1) { sn = g_csrc[p + 1]; vn = g_cval[p + 1]; }
        float4 hs = H4[s * 32 + lane];
        acc.x += v * hs.x; acc.y += v * hs.y; acc.z += v * hs.z; acc.w += v * hs.w;
        s = sn; v = vn; p++;
    }
    float4 b = ((const float4*)bias)[lane];
    acc.x = fmaxf(acc.x + b.x, 0.f); acc.y = fmaxf(acc.y + b.y, 0.f);
    acc.z = fmaxf(acc.z + b.z, 0.f); acc.w = fmaxf(acc.w + b.w, 0.f);
    ((float4*)O)[node * 32 + lane] = acc;
}

// ---------------- agg2 fused with output GEMM -------------------------------
__global__ void k_agg_out(const float* __restrict__ H,
                          const float* __restrict__ bias,
                          const float* __restrict__ W3)
{
    __shared__ __align__(16) float Wt[OUTC * F];  // [c][k]
    int tid = threadIdx.x;
    for (int i = tid; i < OUTC * F; i += blockDim.x) {
        int c = i >> 7, k = i & 127;
        Wt[i] = W3[k * OUTC + c];
    }
    __syncthreads();

    int gt = blockIdx.x * blockDim.x + tid;
    int node = gt >> 5;
    int lane = gt & 31;
    const float4* H4 = (const float4*)H;

    float4 h = H4[node * 32 + lane];
    float ns = g_nself[node];
    float4 acc = make_float4(ns * h.x, ns * h.y, ns * h.z, ns * h.w);

    int p = g_rowptr[node];
    int p1 = g_rowptr[node + 1];
    int s = 0; float v = 0.f;
    if (p < p1) { s = g_csrc[p]; v = g_cval[p]; }
    while (p < p1) {
        int sn = 0; float vn = 0.f;
        if (p + 1 < p1) { sn = g_csrc[p + 1]; vn = g_cval[p + 1]; }
        float4 hs = H4[s * 32 + lane];
        acc.x += v * hs.x; acc.y += v * hs.y; acc.z += v * hs.z; acc.w += v * hs.w;
        s = sn; v = vn; p++;
    }
    float4 b = ((const float4*)bias)[lane];
    acc.x = fmaxf(acc.x + b.x, 0.f); acc.y = fmaxf(acc.y + b.y, 0.f);
    acc.z = fmaxf(acc.z + b.z, 0.f); acc.w = fmaxf(acc.w + b.w, 0.f);

    float o[OUTC];
#pragma unroll
    for (int c = 0; c < OUTC; c++) {
        float4 wv = ((const float4*)Wt)[c * 32 + lane];
        o[c] = acc.x * wv.x + acc.y * wv.y + acc.z * wv.z + acc.w * wv.w;
    }
#pragma unroll
    for (int off = 16; off; off >>= 1)
#pragma unroll
        for (int c = 0; c < OUTC; c++)
            o[c] += __shfl_xor_sync(0xffffffffu, o[c], off);
    if (lane == 0) {
#pragma unroll
        for (int c = 0; c < OUTC; c++) g_h3[node * OUTC + c] = o[c];
    }
}

// ---------------- sparse agg 10-wide + bias + pooling (fused) ---------------
__global__ void k_agg10_pool(const float* __restrict__ b3,
                             const int* __restrict__ batch)
{
    __shared__ float sp[GG * OUTC];
    __shared__ float sc[GG];
    int tid = threadIdx.x;
    for (int j = tid; j < GG * OUTC; j += blockDim.x) sp[j] = 0.f;
    for (int j = tid; j < GG; j += blockDim.x) sc[j] = 0.f;
    __syncthreads();

    int gt = blockIdx.x * blockDim.x + tid;
    int node = gt >> 5;
    int lane = gt & 31;

    float acc = 0.f;
    if (lane < OUTC) acc = g_nself[node] * g_h3[node * OUTC + lane];
    int p = g_rowptr[node];
    int p1 = g_rowptr[node + 1];
    for (; p < p1; p++) {
        int s = g_csrc[p];
        float v = g_cval[p];
        if (lane < OUTC) acc += v * g_h3[s * OUTC + lane];
    }
    int g = batch[node];
    if (lane < OUTC) atomicAdd(&sp[g * OUTC + lane], acc + b3[lane]);
    if (lane == OUTC) atomicAdd(&sc[g], 1.0f);
    __syncthreads();

    for (int j = tid; j < GG * OUTC; j += blockDim.x)
        if (sp[j] != 0.f) atomicAdd(&g_pool[j], sp[j]);
    for (int j = tid; j < GG; j += blockDim.x)
        if (sc[j] != 0.f) atomicAdd(&g_pcnt[j], sc[j]);
}

// ---------------- mean + log_softmax ----------------------------------------
__global__ void k_final(float* __restrict__ out)
{
    int g = threadIdx.x;
    if (g >= GG) return;
    float cnt = fmaxf(g_pcnt[g], 1.0f);
    float v[OUTC];
    float m = -1e30f;
#pragma unroll
    for (int c = 0; c < OUTC; c++) {
        v[c] = g_pool[g * OUTC + c] / cnt;
        m = fmaxf(m, v[c]);
    }
    float s = 0.f;
#pragma unroll
    for (int c = 0; c < OUTC; c++) s += expf(v[c] - m);
    float l = logf(s) + m;
#pragma unroll
    for (int c = 0; c < OUTC; c++) out[g * OUTC + c] = v[c] - l;
}

// ---------------- launch ----------------------------------------------------
extern "C" void kernel_launch(void* const* d_in, const int* in_sizes, int n_in,
                              void* d_out, int out_size)
{
    const float* x     = (const float*)d_in[0];
    const int*   ei    = (const int*)  d_in[1];
    const float* ew    = (const float*)d_in[2];
    const int*   batch = (const int*)  d_in[3];
    const float* W1    = (const float*)d_in[4];
    const float* b1    = (const float*)d_in[5];
    const float* W2    = (const float*)d_in[6];
    const float* b2    = (const float*)d_in[7];
    const float* W3    = (const float*)d_in[8];
    const float* b3    = (const float*)d_in[9];
    float* out = (float*)d_out;

    const int SMEM_MMA = (64 * XS_STRIDE + 128 * WS_STRIDE) * sizeof(float); // 70656
    cudaFuncSetAttribute(k_gemm_mma, cudaFuncAttributeMaxDynamicSharedMemorySize, SMEM_MMA);

    float *h1p, *h2p;
    cudaGetSymbolAddress((void**)&h1p, g_h1);
    cudaGetSymbolAddress((void**)&h2p, g_h2);

    const int nBlkN = (NN + 255) / 256;          // 196
    const int nBlkE = (EE + 255) / 256;          // 3125
    const int nBlkW = (NN * 32) / 256;           // 6250
    const int nBlkT = 2 * ((NN + 63) / 64);      // 1564 (mma gemm, N-split)

    k_zero <<<nBlkN, 256>>>();                                   // my 1
    k_deg  <<<nBlkE, 256>>>(ei, ew);                             // my 2
    k_scan1<<<nBlkN, 256>>>();                                   // my 3
    k_gemm_mma<<<nBlkT, 256, SMEM_MMA>>>(x, W1, h1p, NN);        // my 4 <- ncu sample (6th overall)
    k_scan23<<<nBlkN, 256>>>();                                  // my 5
    k_fill <<<nBlkE, 256>>>(ei, ew);                             // my 6

    k_agg128<<<nBlkW, 256>>>(h1p, h2p, b1);                      // my 7
    k_gemm_mma<<<nBlkT, 256, SMEM_MMA>>>(h2p, W2, h1p, NN);      // my 8
    k_agg_out<<<nBlkW, 256>>>(h1p, b2, W3);                      // my 9
    k_agg10_pool<<<nBlkW, 256>>>(b3, batch);                     // my 10
    k_final<<<1, 64>>>(out);                                     // my 11
}